// round 16
// baseline (speedup 1.0000x reference)
#include <cuda_runtime.h>
#include <cuda_fp16.h>
#include <cstdint>
#include <cstddef>
#include <cstring>

// Problem constants (fixed by the dataset)
#define NV    20000            // vertices per batch
#define NVT   80000            // B * N
#define KN    16               // neighbors
#define MM    9                // kernels
#define CC    64               // in channels
#define OO    64               // out channels
#define GK    576              // GEMM K (M * C)

// Device-global scratch (sanctioned workaround for no-alloc rule)
__device__ float g_uxc[NVT * 12];                        // ux + c (pad 12)
__device__ float g_vxp[NVT * 12];                        // vx     (pad 12)
__device__ __align__(16) __half g_xh[(size_t)NVT * CC];  // x in fp16
__device__ __align__(16) __half g_wb[OO * GK];           // B[o][k] = W[m][o][c]

// ---- packed fp32x2 helpers ----
__device__ __forceinline__ void fma2(unsigned long long& acc,
                                     unsigned long long a,
                                     unsigned long long b) {
    asm("fma.rn.f32x2 %0, %1, %2, %0;" : "+l"(acc) : "l"(a), "l"(b));
}
__device__ __forceinline__ unsigned long long pack2(float x, float y) {
    unsigned long long r;
    asm("mov.b64 %0, {%1, %2};" : "=l"(r) : "f"(x), "f"(y));
    return r;
}
__device__ __forceinline__ float2 unpack2(unsigned long long a) {
    float2 r;
    asm("mov.b64 {%0, %1}, %2;" : "=f"(r.x), "=f"(r.y) : "l"(a));
    return r;
}
// ---- half2 bit-cast helpers ----
__device__ __forceinline__ uint32_t h2u(__half2 h) {
    uint32_t r;
    memcpy(&r, &h, 4);
    return r;
}
__device__ __forceinline__ uint32_t f2h2(float x, float y) {
    return h2u(__floats2half2_rn(x, y));
}
// ---- cp.async helpers ----
__device__ __forceinline__ void cpa16(uint32_t dst_smem, const void* src) {
    asm volatile("cp.async.cg.shared.global [%0], [%1], 16;"
                 :: "r"(dst_smem), "l"(src));
}
__device__ __forceinline__ void cpa_commit() {
    asm volatile("cp.async.commit_group;");
}
__device__ __forceinline__ void cpa_wait0() {
    asm volatile("cp.async.wait_group 0;");
}
__device__ __forceinline__ uint32_t smem_u32(const void* p) {
    uint32_t a;
    asm("{ .reg .u64 t; cvta.to.shared.u64 t, %1; cvt.u32.u64 %0, t; }"
        : "=r"(a) : "l"(p));
    return a;
}
// ---- tensor-core primitives (baseline PTX, sm_75+/80+) ----
__device__ __forceinline__ void ldsm4(uint32_t& r0, uint32_t& r1, uint32_t& r2,
                                      uint32_t& r3, uint32_t addr) {
    asm volatile("ldmatrix.sync.aligned.m8n8.x4.shared.b16 {%0,%1,%2,%3}, [%4];"
                 : "=r"(r0), "=r"(r1), "=r"(r2), "=r"(r3) : "r"(addr));
}
__device__ __forceinline__ void ldsm4t(uint32_t& r0, uint32_t& r1, uint32_t& r2,
                                       uint32_t& r3, uint32_t addr) {
    asm volatile("ldmatrix.sync.aligned.m8n8.x4.trans.shared.b16 {%0,%1,%2,%3}, [%4];"
                 : "=r"(r0), "=r"(r1), "=r"(r2), "=r"(r3) : "r"(addr));
}
__device__ __forceinline__ void mma16816(float* c, uint32_t a0, uint32_t a1,
                                         uint32_t a2, uint32_t a3,
                                         uint32_t b0, uint32_t b1) {
    asm volatile(
        "mma.sync.aligned.m16n8k16.row.col.f32.f16.f16.f32 "
        "{%0,%1,%2,%3}, {%4,%5,%6,%7}, {%8,%9}, {%0,%1,%2,%3};"
        : "+f"(c[0]), "+f"(c[1]), "+f"(c[2]), "+f"(c[3])
        : "r"(a0), "r"(a1), "r"(a2), "r"(a3), "r"(b0), "r"(b1));
}
// per-group chunk rotation (16B granularity): spreads same-row chunks across banks
__device__ __forceinline__ int swzc(int c) {
    return (c & ~7) | ((c + (c >> 3)) & 7);
}

// ---------------------------------------------------------------------------
// Kernel 1 (merged prep): blocks [0, 625) -> lane-PAIR-per-vertex projections
//                         + x -> fp16 copy; blocks [625, +144) -> W -> fp16 B
// ---------------------------------------------------------------------------
#define UVX_BLOCKS 625          // 80000 / 128 vertices per block

__global__ void __launch_bounds__(256)
feast_prep(const float* __restrict__ x, const float* __restrict__ u,
           const float* __restrict__ v, const float* __restrict__ c,
           const float* __restrict__ W) {
    if (blockIdx.x < UVX_BLOCKS) {
        __shared__ float uv_sm[18 * 64];
        __shared__ float c_sm[MM];
        for (int i = threadIdx.x; i < 576; i += 256) {
            uv_sm[i]       = u[i];
            uv_sm[576 + i] = v[i];
        }
        if (threadIdx.x < MM) c_sm[threadIdx.x] = c[threadIdx.x];
        __syncthreads();

        const int pairid = threadIdx.x >> 1;       // vertex within block
        const int hf     = threadIdx.x & 1;        // channel half (0: 0-31)
        const int gi     = blockIdx.x * 128 + pairid;

        unsigned long long xr[16];
        {
            const float4* xp = (const float4*)(x + (size_t)gi * CC + hf * 32);
            #pragma unroll
            for (int i = 0; i < 8; ++i) {
                const float4 t = xp[i];
                xr[2*i]   = pack2(t.x, t.y);
                xr[2*i+1] = pack2(t.z, t.w);
            }
        }
        {
            uint4* dst = (uint4*)(g_xh + (size_t)gi * CC + hf * 32);
            #pragma unroll
            for (int i = 0; i < 4; ++i) {
                const float2 f0 = unpack2(xr[4*i]);
                const float2 f1 = unpack2(xr[4*i+1]);
                const float2 f2 = unpack2(xr[4*i+2]);
                const float2 f3 = unpack2(xr[4*i+3]);
                uint4 o;
                o.x = f2h2(f0.x, f0.y);
                o.y = f2h2(f1.x, f1.y);
                o.z = f2h2(f2.x, f2.y);
                o.w = f2h2(f3.x, f3.y);
                dst[i] = o;
            }
        }
        #pragma unroll
        for (int m = 0; m < MM; ++m) {
            const unsigned long long* um =
                (const unsigned long long*)(uv_sm + m * 64 + hf * 32);
            const unsigned long long* vm =
                (const unsigned long long*)(uv_sm + 576 + m * 64 + hf * 32);
            unsigned long long pu = 0ull, pv = 0ull;
            #pragma unroll
            for (int i = 0; i < 16; ++i) {
                fma2(pu, xr[i], um[i]);
                fma2(pv, xr[i], vm[i]);
            }
            const float2 fu = unpack2(pu);
            const float2 fv = unpack2(pv);
            float su = fu.x + fu.y;
            float sv = fv.x + fv.y;
            su += __shfl_xor_sync(0xffffffffu, su, 1);
            sv += __shfl_xor_sync(0xffffffffu, sv, 1);
            if (hf == 0) {
                g_uxc[gi * 12 + m] = su + c_sm[m];
                g_vxp[gi * 12 + m] = sv;
            }
        }
    } else {
        const int tid = (blockIdx.x - UVX_BLOCKS) * 256 + threadIdx.x;
        if (tid >= MM * OO * CC) return;
        const int cc = tid & 63;
        const int o  = (tid >> 6) & 63;
        const int m  = tid >> 12;
        g_wb[o * GK + m * 64 + cc] = __float2half_rn(W[tid]);
    }
}

// ---------------------------------------------------------------------------
// Kernel 2 (FUSED): gather + softmax + HMMA s (to smem) + HMMA GEMM + bias
// CTA = 32 vertices, TARGET 4 CTAs/SM. Phase 1 uses a warp PAIR per vertex
// (4 concurrent vertices, 8 iterations) -> XS halves to 8 KB, Q to 3 KB.
// Wb buf0 dedicated; buf1 aliases XS. Per-q2 epilogue keeps acc regs at 8.
// ---------------------------------------------------------------------------
// smem layout (bytes from base):
#define S_OFF   0                        // 32 rows x 1168 B (584 halfs)
#define S_ROWB  1168
#define XS_OFF  37376                    // 4 vertices x 16 x 128 B (phase 1)
#define Q_OFF   45568                    // 4 vertices x 16 x 48 B  (phase 1)
#define B0_OFF  48640                    // Wb chunk buf 0 (8 KB, dedicated)
#define FSMEM   56832
// Wb chunk buf 1 aliases XS_OFF (staged only after phase 1 completes)

__global__ void __launch_bounds__(256, 4)
feast_fused(const int* __restrict__ adj, const float* __restrict__ bias,
            float* __restrict__ out) {
    extern __shared__ char smem[];
    const uint32_t sb    = smem_u32(smem);
    const uint32_t sbase = sb + S_OFF;
    const uint32_t bbase[2] = { sb + B0_OFF, sb + XS_OFF };  // buf1 aliases XS

    const int tid  = threadIdx.x;
    const int w    = tid >> 5;
    const int lane = tid & 31;
    const int bv0  = blockIdx.x * 32;

    // stage Wb chunk ch (64 o-rows x 64 halfs, SW128 swizzled) into buffer b
    auto stageB = [&](int ch, int b) {
        const __half* bsrc = g_wb + ch * 64;
        #pragma unroll
        for (int i = 0; i < 2; ++i) {
            const int uu = tid + i * 256;
            const int row = uu >> 3, cu = uu & 7;
            uint32_t off = (uint32_t)(row * 128 + cu * 16);
            off ^= (off >> 3) & 0x70;
            cpa16(bbase[b] + off, bsrc + (size_t)row * GK + cu * 8);
        }
        cpa_commit();
    };
    stageB(0, 0);   // into dedicated buf0; flows in under phase 1

    // ======================= PHASE 1 =======================
    const int p   = w >> 1;                        // warp pair 0..3 (= vertex slot)
    const int sub = w & 1;                         // half within pair
    const uint32_t qtile = sb + Q_OFF + p * 768;   // 16 rows x 48 B
    const uint32_t xtile = sb + XS_OFF + p * 2048; // 16 rows x 128 B
    const int arow = (lane & 7) + ((lane & 16) >> 1);
    const uint32_t aaddr1 = qtile + arow * 48 + ((lane & 8) << 1);
    const int brow = lane & 15;
    const int bsel = lane >> 4;
    const int m1 = lane >> 2;
    const int cw = lane & 3;

    for (int it = 0; it < 8; ++it) {
        const int vrow = it * 4 + p;
        const int gi   = bv0 + vrow;
        const int base = (gi / NV) * NV;

        // both warps: adj + ballot (redundant compute, no communication)
        int a = 0;
        if (lane < 16) a = adj[gi * KN + lane];
        const unsigned bal = __ballot_sync(0xffffffffu, a > 0);
        const int deg = __popc(bal & 0xffffu);
        const int j0  = (a > 0) ? (base + a - 1) : base;

        // softmax: only sub-0 warp, lanes 0-15
        if (sub == 0 && lane < 16) {
            const float validf = (a > 0) ? 1.0f : 0.0f;
            const float4 uc0 = *(const float4*)(g_uxc + gi * 12);
            const float4 uc1 = *(const float4*)(g_uxc + gi * 12 + 4);
            const float4 uc2 = *(const float4*)(g_uxc + gi * 12 + 8);
            const float4 vv0 = *(const float4*)(g_vxp + j0 * 12);
            const float4 vv1 = *(const float4*)(g_vxp + j0 * 12 + 4);
            const float4 vv2 = *(const float4*)(g_vxp + j0 * 12 + 8);
            float l[9];
            l[0] = (uc0.x + vv0.x) * validf; l[1] = (uc0.y + vv0.y) * validf;
            l[2] = (uc0.z + vv0.z) * validf; l[3] = (uc0.w + vv0.w) * validf;
            l[4] = (uc1.x + vv1.x) * validf; l[5] = (uc1.y + vv1.y) * validf;
            l[6] = (uc1.z + vv1.z) * validf; l[7] = (uc1.w + vv1.w) * validf;
            l[8] = (uc2.x + vv2.x) * validf;
            float mx = l[0];
            #pragma unroll
            for (int m = 1; m < 9; ++m) mx = fmaxf(mx, l[m]);
            float e[9], ssum = 0.f;
            #pragma unroll
            for (int m = 0; m < 9; ++m) { e[m] = __expf(l[m] - mx); ssum += e[m]; }
            float r;
            asm("rcp.approx.f32 %0, %1;" : "=f"(r) : "f"(ssum));
            r *= validf;

            uint32_t* qr = (uint32_t*)(smem + Q_OFF + p * 768 + lane * 48);
            qr[0] = f2h2(e[0]*r, e[1]*r);
            qr[1] = f2h2(e[2]*r, e[3]*r);
            qr[2] = f2h2(e[4]*r, e[5]*r);
            qr[3] = f2h2(e[6]*r, e[7]*r);
            qr[4] = f2h2(e[8]*r, 0.f);
            qr[5] = 0u; qr[6] = 0u; qr[7] = 0u;
        }

        // gather: each warp fills its 8 rows (k = sub*8 .. +7), 2 units/lane
        #pragma unroll
        for (int u2 = 0; u2 < 2; ++u2) {
            const int idx  = lane + u2 * 32;           // 0..63
            const int row8 = idx >> 3;                 // 0..7
            const int c16  = idx & 7;                  // 16B chunk
            const int krow = sub * 8 + row8;           // global row in tile
            const int jr   = __shfl_sync(0xffffffffu, j0, krow);
            const uint4 val = *(const uint4*)(g_xh + (size_t)jr * CC + c16 * 8);
            const uint32_t off = krow * 128 + (((c16 ^ krow) & 7) << 4);
            *(uint4*)(smem + XS_OFF + p * 2048 + off) = val;
        }
        asm volatile("bar.sync %0, 64;" :: "r"(p + 1) : "memory");

        // MMA: both warps; sub covers cols sub*32 .. +31 (chunks 4sub..4sub+3)
        uint32_t a0, a1, a2, a3;
        ldsm4t(a0, a1, a2, a3, aaddr1);

        const float scl = (deg > 0) ? (1.0f / (float)deg) : 0.0f;
        uint32_t* srow = (uint32_t*)(smem + S_OFF + vrow * S_ROWB);

        #pragma unroll
        for (int q2 = 0; q2 < 2; ++q2) {
            const int cb = sub * 4 + q2 * 2;           // chunk base
            const int chunk = cb + bsel;
            const uint32_t baddr =
                xtile + brow * 128 + (((chunk ^ brow) & 7) << 4);
            uint32_t b0, b1, b2, b3;
            ldsm4t(b0, b1, b2, b3, baddr);
            float acc[2][4] = {{0.f,0.f,0.f,0.f},{0.f,0.f,0.f,0.f}};
            mma16816(acc[0], a0, a1, a2, a3, b0, b1);
            mma16816(acc[1], a0, a1, a2, a3, b2, b3);
            #pragma unroll
            for (int j = 0; j < 2; ++j) {
                const int nb = cb + j;
                const int c = m1 * 8 + nb;
                srow[swzc(c) * 4 + cw] = f2h2(acc[j][0] * scl, acc[j][1] * scl);
                if (m1 == 0) {
                    const int c8 = 64 + nb;
                    srow[swzc(c8) * 4 + cw] =
                        f2h2(acc[j][2] * scl, acc[j][3] * scl);
                }
            }
        }
        asm volatile("bar.sync %0, 64;" :: "r"(p + 1) : "memory");
    }
    __syncthreads();   // s tile complete; XS/Q dead from here

    // ======================= PHASE 2 =======================
    // warp: rows rg*16 (rg = w>>2), cols cg4*16 (cg4 = w&3)
    const int rg  = w >> 2;
    const int cg4 = w & 3;
    const int grp = lane >> 3;
    const int rr  = lane & 7;
    const int mrow = (grp & 1) * 8 + rr;
    const int mcol = (grp >> 1) * 16;

    float acc2[2][4];
    #pragma unroll
    for (int j = 0; j < 2; ++j)
        #pragma unroll
        for (int pp = 0; pp < 4; ++pp) acc2[j][pp] = 0.f;

    const uint32_t arowaddr = sbase + (rg * 16 + mrow) * S_ROWB;

    for (int ch = 0; ch < 9; ++ch) {
        cpa_wait0();
        __syncthreads();   // chunk ch resident; prev buf free

        if (ch < 8) stageB(ch + 1, (ch + 1) & 1);   // buf1 = XS region (dead)

        const uint32_t bb = bbase[ch & 1];
        #pragma unroll
        for (int k16 = 0; k16 < 4; ++k16) {
            const int c = ch * 8 + k16 * 2 + (mcol >> 4);
            uint32_t a0, a1, a2, a3;
            ldsm4(a0, a1, a2, a3, arowaddr + swzc(c) * 16);
            uint32_t boff = (uint32_t)((cg4 * 16 + mrow) * 128 + mcol + k16 * 32);
            boff ^= (boff >> 3) & 0x70;
            uint32_t b0, b1, b2, b3;
            ldsm4(b0, b1, b2, b3, bb + boff);
            mma16816(acc2[0], a0, a1, a2, a3, b0, b2);
            mma16816(acc2[1], a0, a1, a2, a3, b1, b3);
        }
    }

    // ---- epilogue: C frags + bias -> gmem ----
    const int crow = bv0 + rg * 16 + (lane >> 2);
    const int ccol = cg4 * 16 + (lane & 3) * 2;
    #pragma unroll
    for (int j = 0; j < 2; ++j) {
        const int nb = ccol + j * 8;
        const float2 bv = *(const float2*)(bias + nb);
        *(float2*)(out + (size_t)crow * OO + nb) =
            make_float2(acc2[j][0] + bv.x, acc2[j][1] + bv.y);
        *(float2*)(out + (size_t)(crow + 8) * OO + nb) =
            make_float2(acc2[j][2] + bv.x, acc2[j][3] + bv.y);
    }
}

// ---------------------------------------------------------------------------
// Host launcher (graph-capturable: kernel launches only)
// ---------------------------------------------------------------------------
extern "C" void kernel_launch(void* const* d_in, const int* in_sizes, int n_in,
                              void* d_out, int out_size) {
    const float* x   = (const float*)d_in[0];  // [B,N,C]
    const int*   adj = (const int*)  d_in[1];  // [B,N,K]
    const float* W   = (const float*)d_in[2];  // [M,O,C]
    const float* b   = (const float*)d_in[3];  // [O]
    const float* u   = (const float*)d_in[4];  // [M,C]
    const float* v   = (const float*)d_in[5];  // [M,C]
    const float* c   = (const float*)d_in[6];  // [M]
    float* out = (float*)d_out;

    feast_prep<<<UVX_BLOCKS + (MM * OO * CC + 255) / 256, 256>>>(x, u, v, c, W);

    cudaFuncSetAttribute(feast_fused, cudaFuncAttributeMaxDynamicSharedMemorySize,
                         FSMEM);
    feast_fused<<<NVT / 32, 256, FSMEM>>>(adj, b, out);
}

// round 17
// speedup vs baseline: 1.1258x; 1.1258x over previous
#include <cuda_runtime.h>
#include <cuda_fp16.h>
#include <cstdint>
#include <cstddef>
#include <cstring>

// Problem constants (fixed by the dataset)
#define NV    20000            // vertices per batch
#define NVT   80000            // B * N
#define KN    16               // neighbors
#define MM    9                // kernels
#define CC    64               // in channels
#define OO    64               // out channels
#define GK    576              // GEMM K (M * C)

// Device-global scratch (sanctioned workaround for no-alloc rule)
__device__ float g_uxc[NVT * 12];                        // ux + c (pad 12)
__device__ float g_vxp[NVT * 12];                        // vx     (pad 12)
__device__ __align__(16) __half g_xh[(size_t)NVT * CC];  // x in fp16
// W in HMMA-fragment order: uint4 per (k16-step t, col-group cg4, lane):
//   .x=b0(n=l/4,k=2(l%4))  .y=b1(n+8)  .z=b2(k+8)  .w=b3(n+8,k+8), half2 each
__device__ __align__(16) uint4 g_wbf[36 * 4 * 32];

// ---- packed fp32x2 helpers ----
__device__ __forceinline__ void fma2(unsigned long long& acc,
                                     unsigned long long a,
                                     unsigned long long b) {
    asm("fma.rn.f32x2 %0, %1, %2, %0;" : "+l"(acc) : "l"(a), "l"(b));
}
__device__ __forceinline__ unsigned long long pack2(float x, float y) {
    unsigned long long r;
    asm("mov.b64 %0, {%1, %2};" : "=l"(r) : "f"(x), "f"(y));
    return r;
}
__device__ __forceinline__ float2 unpack2(unsigned long long a) {
    float2 r;
    asm("mov.b64 {%0, %1}, %2;" : "=f"(r.x), "=f"(r.y) : "l"(a));
    return r;
}
// ---- half2 bit-cast helpers ----
__device__ __forceinline__ uint32_t h2u(__half2 h) {
    uint32_t r;
    memcpy(&r, &h, 4);
    return r;
}
__device__ __forceinline__ uint32_t f2h2(float x, float y) {
    return h2u(__floats2half2_rn(x, y));
}
__device__ __forceinline__ uint32_t smem_u32(const void* p) {
    uint32_t a;
    asm("{ .reg .u64 t; cvta.to.shared.u64 t, %1; cvt.u32.u64 %0, t; }"
        : "=r"(a) : "l"(p));
    return a;
}
// ---- tensor-core primitives (baseline PTX, sm_75+/80+) ----
__device__ __forceinline__ void ldsm4(uint32_t& r0, uint32_t& r1, uint32_t& r2,
                                      uint32_t& r3, uint32_t addr) {
    asm volatile("ldmatrix.sync.aligned.m8n8.x4.shared.b16 {%0,%1,%2,%3}, [%4];"
                 : "=r"(r0), "=r"(r1), "=r"(r2), "=r"(r3) : "r"(addr));
}
__device__ __forceinline__ void ldsm4t(uint32_t& r0, uint32_t& r1, uint32_t& r2,
                                       uint32_t& r3, uint32_t addr) {
    asm volatile("ldmatrix.sync.aligned.m8n8.x4.trans.shared.b16 {%0,%1,%2,%3}, [%4];"
                 : "=r"(r0), "=r"(r1), "=r"(r2), "=r"(r3) : "r"(addr));
}
__device__ __forceinline__ void mma16816(float* c, uint32_t a0, uint32_t a1,
                                         uint32_t a2, uint32_t a3,
                                         uint32_t b0, uint32_t b1) {
    asm volatile(
        "mma.sync.aligned.m16n8k16.row.col.f32.f16.f16.f32 "
        "{%0,%1,%2,%3}, {%4,%5,%6,%7}, {%8,%9}, {%0,%1,%2,%3};"
        : "+f"(c[0]), "+f"(c[1]), "+f"(c[2]), "+f"(c[3])
        : "r"(a0), "r"(a1), "r"(a2), "r"(a3), "r"(b0), "r"(b1));
}
// per-group chunk rotation (16B granularity): spreads same-row chunks across banks
__device__ __forceinline__ int swzc(int c) {
    return (c & ~7) | ((c + (c >> 3)) & 7);
}

// ---------------------------------------------------------------------------
// Kernel 1 (merged prep): blocks [0, 625) -> lane-PAIR-per-vertex projections
//                         + x -> fp16 copy; blocks [625, +72) -> W -> g_wbf
// ---------------------------------------------------------------------------
#define UVX_BLOCKS 625          // 80000 / 128 vertices per block
#define WBF_WORDS  (36 * 4 * 32 * 4)     // 18432 uint32 fragment words

__global__ void __launch_bounds__(256)
feast_prep(const float* __restrict__ x, const float* __restrict__ u,
           const float* __restrict__ v, const float* __restrict__ c,
           const float* __restrict__ W) {
    if (blockIdx.x < UVX_BLOCKS) {
        __shared__ float uv_sm[18 * 64];
        __shared__ float c_sm[MM];
        for (int i = threadIdx.x; i < 576; i += 256) {
            uv_sm[i]       = u[i];
            uv_sm[576 + i] = v[i];
        }
        if (threadIdx.x < MM) c_sm[threadIdx.x] = c[threadIdx.x];
        __syncthreads();

        const int pairid = threadIdx.x >> 1;       // vertex within block
        const int hf     = threadIdx.x & 1;        // channel half (0: 0-31)
        const int gi     = blockIdx.x * 128 + pairid;

        unsigned long long xr[16];
        {
            const float4* xp = (const float4*)(x + (size_t)gi * CC + hf * 32);
            #pragma unroll
            for (int i = 0; i < 8; ++i) {
                const float4 t = xp[i];
                xr[2*i]   = pack2(t.x, t.y);
                xr[2*i+1] = pack2(t.z, t.w);
            }
        }
        {
            uint4* dst = (uint4*)(g_xh + (size_t)gi * CC + hf * 32);
            #pragma unroll
            for (int i = 0; i < 4; ++i) {
                const float2 f0 = unpack2(xr[4*i]);
                const float2 f1 = unpack2(xr[4*i+1]);
                const float2 f2 = unpack2(xr[4*i+2]);
                const float2 f3 = unpack2(xr[4*i+3]);
                uint4 o;
                o.x = f2h2(f0.x, f0.y);
                o.y = f2h2(f1.x, f1.y);
                o.z = f2h2(f2.x, f2.y);
                o.w = f2h2(f3.x, f3.y);
                dst[i] = o;
            }
        }
        #pragma unroll
        for (int m = 0; m < MM; ++m) {
            const unsigned long long* um =
                (const unsigned long long*)(uv_sm + m * 64 + hf * 32);
            const unsigned long long* vm =
                (const unsigned long long*)(uv_sm + 576 + m * 64 + hf * 32);
            unsigned long long pu = 0ull, pv = 0ull;
            #pragma unroll
            for (int i = 0; i < 16; ++i) {
                fma2(pu, xr[i], um[i]);
                fma2(pv, xr[i], vm[i]);
            }
            const float2 fu = unpack2(pu);
            const float2 fv = unpack2(pv);
            float su = fu.x + fu.y;
            float sv = fv.x + fv.y;
            su += __shfl_xor_sync(0xffffffffu, su, 1);
            sv += __shfl_xor_sync(0xffffffffu, sv, 1);
            if (hf == 0) {
                g_uxc[gi * 12 + m] = su + c_sm[m];
                g_vxp[gi * 12 + m] = sv;
            }
        }
    } else {
        // W -> fragment-ordered fp16 (one thread per 32-bit frag word)
        const int tid = (blockIdx.x - UVX_BLOCKS) * 256 + threadIdx.x;
        if (tid >= WBF_WORDS) return;
        const int r   = tid & 3;
        const int l   = (tid >> 2) & 31;
        const int cg4 = (tid >> 7) & 3;
        const int t   = tid >> 9;
        const int n   = cg4 * 16 + (r & 1) * 8 + (l >> 2);
        const int k   = 16 * t + ((r >> 1) & 1) * 8 + 2 * (l & 3);
        const int m   = k >> 6;
        const int cc  = k & 63;
        const float v0 = W[m * 4096 + n * 64 + cc];
        const float v1 = W[m * 4096 + n * 64 + cc + 1];
        ((uint32_t*)g_wbf)[tid] = f2h2(v0, v1);
    }
}

// ---------------------------------------------------------------------------
// Kernel 2 (FUSED): gather + softmax + HMMA s (to smem) + HMMA GEMM + bias
// CTA = 32 vertices, 3 CTAs/SM. Phase 1 = round-15 shape (warp per vertex,
// 4 iterations). Phase 2 = single uniform loop; B frags straight from gmem
// (g_wbf), NO staging, NO per-chunk barriers. One __syncthreads total.
// ---------------------------------------------------------------------------
// smem layout (bytes from base):
#define S_OFF   0                        // 32 rows x 1168 B (584 halfs)
#define S_ROWB  1168
#define XS_OFF  37376                    // 8 warps x 16 x 128 B (phase 1 only)
#define Q_OFF   53760                    // 8 warps x 16 x 48 B  (phase 1 only)
#define FSMEM   59904

__global__ void __launch_bounds__(256, 3)
feast_fused(const int* __restrict__ adj, const float* __restrict__ bias,
            float* __restrict__ out) {
    extern __shared__ char smem[];
    const uint32_t sb    = smem_u32(smem);
    const uint32_t sbase = sb + S_OFF;

    const int tid  = threadIdx.x;
    const int w    = tid >> 5;
    const int lane = tid & 31;
    const int bv0  = blockIdx.x * 32;

    // ======================= PHASE 1 =======================
    const uint32_t qbase = sb + Q_OFF + w * (16 * 48);
    const uint32_t xbase = sb + XS_OFF + w * (16 * 128);
    const int arow = (lane & 7) + ((lane & 16) >> 1);
    const uint32_t aaddr1 = qbase + arow * 48 + ((lane & 8) << 1);
    const int brow = lane & 15;
    const int bsel = lane >> 4;

    for (int it = 0; it < 4; ++it) {
        const int vrow = it * 8 + w;
        const int gi   = bv0 + vrow;
        const int base = (gi / NV) * NV;

        int a = 0;
        if (lane < 16) a = adj[gi * KN + lane];
        const unsigned bal = __ballot_sync(0xffffffffu, a > 0);
        const int deg = __popc(bal & 0xffffu);
        const int j0  = (a > 0) ? (base + a - 1) : base;

        if (lane < 16) {
            const float validf = (a > 0) ? 1.0f : 0.0f;
            const float4 uc0 = *(const float4*)(g_uxc + gi * 12);
            const float4 uc1 = *(const float4*)(g_uxc + gi * 12 + 4);
            const float4 uc2 = *(const float4*)(g_uxc + gi * 12 + 8);
            const float4 vv0 = *(const float4*)(g_vxp + j0 * 12);
            const float4 vv1 = *(const float4*)(g_vxp + j0 * 12 + 4);
            const float4 vv2 = *(const float4*)(g_vxp + j0 * 12 + 8);
            float l[9];
            l[0] = (uc0.x + vv0.x) * validf; l[1] = (uc0.y + vv0.y) * validf;
            l[2] = (uc0.z + vv0.z) * validf; l[3] = (uc0.w + vv0.w) * validf;
            l[4] = (uc1.x + vv1.x) * validf; l[5] = (uc1.y + vv1.y) * validf;
            l[6] = (uc1.z + vv1.z) * validf; l[7] = (uc1.w + vv1.w) * validf;
            l[8] = (uc2.x + vv2.x) * validf;
            float mx = l[0];
            #pragma unroll
            for (int m = 1; m < 9; ++m) mx = fmaxf(mx, l[m]);
            float e[9], ssum = 0.f;
            #pragma unroll
            for (int m = 0; m < 9; ++m) { e[m] = __expf(l[m] - mx); ssum += e[m]; }
            float r;
            asm("rcp.approx.f32 %0, %1;" : "=f"(r) : "f"(ssum));
            r *= validf;

            uint32_t* qr = (uint32_t*)(smem + Q_OFF + (w * 16 + lane) * 48);
            qr[0] = f2h2(e[0]*r, e[1]*r);
            qr[1] = f2h2(e[2]*r, e[3]*r);
            qr[2] = f2h2(e[4]*r, e[5]*r);
            qr[3] = f2h2(e[6]*r, e[7]*r);
            qr[4] = f2h2(e[8]*r, 0.f);
            qr[5] = 0u; qr[6] = 0u; qr[7] = 0u;
        }
        __syncwarp();

        // gather 16 neighbor fp16 rows into swizzled xs tile
        #pragma unroll
        for (int p = 0; p < 4; ++p) {
            const int idx = lane + p * 32;
            const int row = idx >> 3;
            const int c16 = idx & 7;
            const int jr  = __shfl_sync(0xffffffffu, j0, row);
            const uint4 val = *(const uint4*)(g_xh + (size_t)jr * CC + c16 * 8);
            const uint32_t off = row * 128 + (((c16 ^ row) & 7) << 4);
            *(uint4*)(smem + XS_OFF + w * (16 * 128) + off) = val;
        }
        __syncwarp();

        uint32_t a0, a1, a2, a3;
        ldsm4t(a0, a1, a2, a3, aaddr1);

        float acc[8][4];
        #pragma unroll
        for (int nb = 0; nb < 8; ++nb)
            #pragma unroll
            for (int p = 0; p < 4; ++p) acc[nb][p] = 0.f;

        #pragma unroll
        for (int q = 0; q < 4; ++q) {
            const int chunk = 2 * q + bsel;
            const uint32_t baddr =
                xbase + brow * 128 + (((chunk ^ brow) & 7) << 4);
            uint32_t b0, b1, b2, b3;
            ldsm4t(b0, b1, b2, b3, baddr);
            mma16816(acc[2*q],     a0, a1, a2, a3, b0, b1);
            mma16816(acc[2*q + 1], a0, a1, a2, a3, b2, b3);
        }

        // epilogue -> smem s tile (rotated chunks, conflict-free)
        const float scl = (deg > 0) ? (1.0f / (float)deg) : 0.0f;
        uint32_t* srow = (uint32_t*)(smem + S_OFF + vrow * S_ROWB);
        const int m1 = lane >> 2;
        const int cw = lane & 3;
        #pragma unroll
        for (int nb = 0; nb < 8; ++nb) {
            const int c = m1 * 8 + nb;
            srow[swzc(c) * 4 + cw] = f2h2(acc[nb][0] * scl, acc[nb][1] * scl);
            if (m1 == 0) {
                const int c8 = 64 + nb;
                srow[swzc(c8) * 4 + cw] = f2h2(acc[nb][2] * scl, acc[nb][3] * scl);
            }
        }
        __syncwarp();
    }
    __syncthreads();   // s tile complete (the ONLY block-wide barrier)

    // ======================= PHASE 2 =======================
    // warp: rows rg*16 (rg = w>>2), cols cg4*16 (cg4 = w&3)
    const int rg  = w >> 2;
    const int cg4 = w & 3;
    const int grp = lane >> 3;
    const int rr  = lane & 7;
    const int mrow = (grp & 1) * 8 + rr;
    const int mcol = (grp >> 1) * 16;

    float acc2[2][4];
    #pragma unroll
    for (int j = 0; j < 2; ++j)
        #pragma unroll
        for (int p = 0; p < 4; ++p) acc2[j][p] = 0.f;

    const uint32_t arowaddr = sbase + (rg * 16 + mrow) * S_ROWB;
    const uint4* bfrag = g_wbf + cg4 * 32 + lane;    // + t*128 per step

    #pragma unroll 6
    for (int t = 0; t < 36; ++t) {
        const int c = 2 * t + (mcol >> 4);
        uint32_t a0, a1, a2, a3;
        ldsm4(a0, a1, a2, a3, arowaddr + swzc(c) * 16);
        const uint4 bf = bfrag[t * 128];
        mma16816(acc2[0], a0, a1, a2, a3, bf.x, bf.z);
        mma16816(acc2[1], a0, a1, a2, a3, bf.y, bf.w);
    }

    // ---- epilogue: C frags + bias -> gmem ----
    const int crow = bv0 + rg * 16 + (lane >> 2);
    const int ccol = cg4 * 16 + (lane & 3) * 2;
    #pragma unroll
    for (int j = 0; j < 2; ++j) {
        const int nb = ccol + j * 8;
        const float2 bv = *(const float2*)(bias + nb);
        *(float2*)(out + (size_t)crow * OO + nb) =
            make_float2(acc2[j][0] + bv.x, acc2[j][1] + bv.y);
        *(float2*)(out + (size_t)(crow + 8) * OO + nb) =
            make_float2(acc2[j][2] + bv.x, acc2[j][3] + bv.y);
    }
}

// ---------------------------------------------------------------------------
// Host launcher (graph-capturable: kernel launches only)
// ---------------------------------------------------------------------------
extern "C" void kernel_launch(void* const* d_in, const int* in_sizes, int n_in,
                              void* d_out, int out_size) {
    const float* x   = (const float*)d_in[0];  // [B,N,C]
    const int*   adj = (const int*)  d_in[1];  // [B,N,K]
    const float* W   = (const float*)d_in[2];  // [M,O,C]
    const float* b   = (const float*)d_in[3];  // [O]
    const float* u   = (const float*)d_in[4];  // [M,C]
    const float* v   = (const float*)d_in[5];  // [M,C]
    const float* c   = (const float*)d_in[6];  // [M]
    float* out = (float*)d_out;

    feast_prep<<<UVX_BLOCKS + (WBF_WORDS + 255) / 256, 256>>>(x, u, v, c, W);

    cudaFuncSetAttribute(feast_fused, cudaFuncAttributeMaxDynamicSharedMemorySize,
                         FSMEM);
    feast_fused<<<NVT / 32, 256, FSMEM>>>(adj, b, out);
}